// round 11
// baseline (speedup 1.0000x reference)
#include <cuda_runtime.h>
#include <math.h>

#define RF 129
#define NF (RF*RF*RF)
#define H 64

// ---- scratch (device globals; no allocations allowed) ----
__device__ float g_bufA[NF];
__device__ float g_bufB[NF];
__device__ float g_true[NF];
__device__ unsigned char g_calc[NF];   // "calculated" at full 129^3 lattice
__device__ unsigned char g_mB[NF];     // boundary mask
__device__ unsigned char g_mA[NF];     // conflict buffer 0
__device__ unsigned char g_mC[NF];     // conflict buffer 1
__device__ int g_wl[NF];               // worklist of active voxel indices
__device__ int g_count;                // worklist length

// ---- packed fp32x2 helpers (Blackwell FFMA2 path) ----
__device__ __forceinline__ unsigned long long pack2(float a, float b) {
    unsigned long long r;
    asm("mov.b64 %0, {%1, %2};" : "=l"(r) : "f"(a), "f"(b));
    return r;
}
__device__ __forceinline__ unsigned long long fma2(unsigned long long a,
                                                   unsigned long long b,
                                                   unsigned long long c) {
    unsigned long long r;
    asm("fma.rn.f32x2 %0, %1, %2, %3;" : "=l"(r) : "l"(a), "l"(b), "l"(c));
    return r;
}
__device__ __forceinline__ void unpack2(unsigned long long v, float& a, float& b) {
    asm("mov.b64 {%0, %1}, %2;" : "=f"(a), "=f"(b) : "l"(v));
}

// ---------------------------------------------------------------------------
// init: calculated seed lattice (::8) + seed worklist with dense 17^3 indices
// ---------------------------------------------------------------------------
__global__ void k_init_calc() {
    int idx = blockIdx.x * blockDim.x + threadIdx.x;
    if (idx >= NF) return;
    int k = idx % RF;
    int j = (idx / RF) % RF;
    int i = idx / (RF * RF);
    g_calc[idx] = ((i & 7) == 0 && (j & 7) == 0 && (k & 7) == 0) ? 1 : 0;
    if (idx < 17 * 17 * 17) g_wl[idx] = idx;
    if (idx == 0) g_count = 17 * 17 * 17;
}

// ---------------------------------------------------------------------------
// FUSED: upsample (exact half-step trilinear) + fractional mask (shared tile,
// halo 1) + boundary = dilate(frac) & ~calc + zero conflict buffers.
// 8^3 interior tiles, 512 threads.
// ---------------------------------------------------------------------------
__global__ void k_up_boundary(const float* __restrict__ prev, float* __restrict__ occ,
                              int R, int Rp, int s) {
    __shared__ unsigned char s_frac[1000];   // 10^3
    const int bx = blockIdx.x * 8, by = blockIdx.y * 8, bz = blockIdx.z * 8;
    const int tid = threadIdx.x + threadIdx.y * 8 + threadIdx.z * 64;
    if (bx == 0 && by == 0 && bz == 0 && tid == 0) g_count = 0;  // reset worklist

    const int RpRp = Rp * Rp;
    for (int t = tid; t < 1000; t += 512) {
        int c = t % 10, b = (t / 10) % 10, a = t / 100;
        int qi = bz + a - 1, qj = by + b - 1, qk = bx + c - 1;
        unsigned char f = 0;
        if ((unsigned)qi < (unsigned)R && (unsigned)qj < (unsigned)R &&
            (unsigned)qk < (unsigned)R) {
            int i0 = qi >> 1, j0 = qj >> 1, k0 = qk >> 1;
            int di = qi & 1, dj = qj & 1, dk = qk & 1;
            int pos = 0, cnt = 0;
            for (int dz = 0; dz <= di; dz++)
                for (int dy = 0; dy <= dj; dy++)
                    for (int dx = 0; dx <= dk; dx++) {
                        float v = prev[(i0 + dz) * RpRp + (j0 + dy) * Rp + (k0 + dx)];
                        pos += (v > 0.5f) ? 1 : 0;
                        cnt++;
                    }
            f = (pos != 0 && pos != cnt) ? 1 : 0;
        }
        s_frac[t] = f;
    }
    __syncthreads();

    int i = bz + threadIdx.z, j = by + threadIdx.y, k = bx + threadIdx.x;
    if (i >= R || j >= R || k >= R) return;
    int idx = i * R * R + j * R + k;

    // exact interp (same summation order; validated rel_err 5e-8)
    {
        int i0 = i >> 1, j0 = j >> 1, k0 = k >> 1;
        int di = i & 1, dj = j & 1, dk = k & 1;
        float sum = 0.0f;
        int cnt = 0;
        for (int dz = 0; dz <= di; dz++)
            for (int dy = 0; dy <= dj; dy++)
                for (int dx = 0; dx <= dk; dx++) {
                    sum += prev[(i0 + dz) * RpRp + (j0 + dy) * Rp + (k0 + dx)];
                    cnt++;
                }
        occ[idx] = sum / (float)cnt;
    }
    g_mA[idx] = 0;
    g_mC[idx] = 0;

    // boundary = dilate27(frac) & ~calc[strided]
    unsigned char v = 0;
    int la = threadIdx.z, lb = threadIdx.y, lc = threadIdx.x;
    for (int a = 0; a < 3 && !v; a++)
        for (int b = 0; b < 3 && !v; b++)
            for (int c = 0; c < 3; c++)
                if (s_frac[(la + a) * 100 + (lb + b) * 10 + (lc + c)]) { v = 1; break; }
    if (v && g_calc[(i * s) * RF * RF + (j * s) * RF + (k * s)]) v = 0;
    g_mB[idx] = v;
}

// ---------------------------------------------------------------------------
// FUSED: dilate^2(boundary) + worklist append. Shared tile halo 2 (12^3),
// whole-block early exit when the window is empty.
// ---------------------------------------------------------------------------
__global__ void k_dilate2_scan(int R) {
    __shared__ unsigned char s_m[1728];   // 12^3
    __shared__ unsigned char s_d[1000];   // 10^3
    const int bx = blockIdx.x * 8, by = blockIdx.y * 8, bz = blockIdx.z * 8;
    const int tid = threadIdx.x + threadIdx.y * 8 + threadIdx.z * 64;
    const int RR = R * R;

    int any = 0;
    for (int t = tid; t < 1728; t += 512) {
        int c = t % 12, b = (t / 12) % 12, a = t / 144;
        int qi = bz + a - 2, qj = by + b - 2, qk = bx + c - 2;
        unsigned char val = 0;
        if ((unsigned)qi < (unsigned)R && (unsigned)qj < (unsigned)R &&
            (unsigned)qk < (unsigned)R)
            val = g_mB[qi * RR + qj * R + qk];
        s_m[t] = val;
        any |= val;
    }
    if (__syncthreads_or(any) == 0) return;   // empty window: no work

    for (int t = tid; t < 1000; t += 512) {
        int c = t % 10, b = (t / 10) % 10, a = t / 100;
        unsigned char v = 0;
        for (int da = 0; da < 3 && !v; da++)
            for (int db = 0; db < 3 && !v; db++)
                for (int dc = 0; dc < 3; dc++)
                    if (s_m[(a + da) * 144 + (b + db) * 12 + (c + dc)]) { v = 1; break; }
        s_d[t] = v;
    }
    __syncthreads();

    int i = bz + threadIdx.z, j = by + threadIdx.y, k = bx + threadIdx.x;
    unsigned char v = 0;
    int idx = 0;
    if (i < R && j < R && k < R) {
        idx = i * RR + j * R + k;
        int la = threadIdx.z, lb = threadIdx.y, lc = threadIdx.x;
        for (int a = 0; a < 3 && !v; a++)
            for (int b = 0; b < 3 && !v; b++)
                for (int c = 0; c < 3; c++)
                    if (s_d[(la + a) * 100 + (lb + b) * 10 + (lc + c)]) { v = 1; break; }
    }
    unsigned ballot = __ballot_sync(0xffffffffu, v != 0);
    if (v) {
        int lane = tid & 31;
        int leader = __ffs(ballot) - 1;
        int base = 0;
        if (lane == leader) base = atomicAdd(&g_count, __popc(ballot));
        base = __shfl_sync(0xffffffffu, base, leader);
        g_wl[base + __popc(ballot & ((1u << lane) - 1u))] = idx;
    }
}

// ---------------------------------------------------------------------------
// worklist MLP: 2 points/thread, packed fp32x2 FMA with pre-duplicated packed
// weights in shared (no pack2 in the hot loop), 2-accumulator ILP, grid-stride.
// s_w2d is 16B-aligned: the ulonglong2 (LDS.128) loads REQUIRE it.
// ---------------------------------------------------------------------------
__global__ void __launch_bounds__(128, 2)
k_mlp_list(const float* __restrict__ w1, const float* __restrict__ b1,
           const float* __restrict__ w2, const float* __restrict__ b2,
           const float* __restrict__ w3, const float* __restrict__ b3,
           float* __restrict__ out, int R, int s) {
    __shared__ float s_w1[3 * H];
    __shared__ float s_b1[H];
    __shared__ float s_b2[H];
    __shared__ float s_w3[H];
    __shared__ float s_b3f;
    __shared__ __align__(16) unsigned long long s_w2d[H * H];  // dup packed (w,w)

    const int count = g_count;
    const int npairs = (count + 1) >> 1;
    if ((int)(blockIdx.x * blockDim.x) >= npairs) return;  // tail blocks

    for (int t = threadIdx.x; t < 3 * H; t += blockDim.x) s_w1[t] = w1[t];
    for (int t = threadIdx.x; t < H; t += blockDim.x) {
        s_b1[t] = b1[t];
        s_b2[t] = b2[t];
        s_w3[t] = w3[t];
    }
    for (int t = threadIdx.x; t < H * H; t += blockDim.x) {
        int jj = t >> 6, u = t & 63;             // s_w2d[jj*H+u] = dup(w2[u][jj])
        float w = w2[u * H + jj];
        s_w2d[t] = pack2(w, w);
    }
    if (threadIdx.x == 0) s_b3f = b3[0];
    __syncthreads();

    const int stride = gridDim.x * blockDim.x;
    for (int pair = blockIdx.x * blockDim.x + threadIdx.x; pair < npairs;
         pair += stride) {
        int ia = g_wl[2 * pair];
        int ib = (2 * pair + 1 < count) ? g_wl[2 * pair + 1] : ia;

        const float sc = 2.0f / 129.0f;
        int ka = ia % R, ja = (ia / R) % R, iia = ia / (R * R);
        int kb = ib % R, jb = (ib / R) % R, iib = ib / (R * R);
        float pxa = ((float)(ka * s) + 0.5f) * sc - 1.0f;
        float pya = ((float)(ja * s) + 0.5f) * sc - 1.0f;
        float pza = ((float)(iia * s) + 0.5f) * sc - 1.0f;
        float pxb = ((float)(kb * s) + 0.5f) * sc - 1.0f;
        float pyb = ((float)(jb * s) + 0.5f) * sc - 1.0f;
        float pzb = ((float)(iib * s) + 0.5f) * sc - 1.0f;

        // layer 1: scalar, packed into f32x2
        unsigned long long h1p[H];
#pragma unroll
        for (int u = 0; u < H; u++) {
            float wx = s_w1[u], wy = s_w1[H + u], wz = s_w1[2 * H + u], bb = s_b1[u];
            float va = fmaf(pza, wz, fmaf(pya, wy, fmaf(pxa, wx, bb)));
            float vb = fmaf(pzb, wz, fmaf(pyb, wy, fmaf(pxb, wx, bb)));
            h1p[u] = pack2(fmaxf(va, 0.0f), fmaxf(vb, 0.0f));
        }

        // layer 2 + output accumulate: pure LDS.128 + fma2, 2 chains
        float oA = s_b3f, oB = s_b3f;
#pragma unroll 1
        for (int jj = 0; jj < H; jj += 2) {
            unsigned long long acc0 = pack2(s_b2[jj], s_b2[jj]);
            unsigned long long acc1 = pack2(s_b2[jj + 1], s_b2[jj + 1]);
            const ulonglong2* r0 = (const ulonglong2*)&s_w2d[jj * H];
            const ulonglong2* r1 = (const ulonglong2*)&s_w2d[jj * H + H];
#pragma unroll
            for (int u = 0; u < H / 2; u++) {
                ulonglong2 w0 = r0[u];
                acc0 = fma2(h1p[2 * u], w0.x, acc0);
                acc0 = fma2(h1p[2 * u + 1], w0.y, acc0);
                ulonglong2 wq = r1[u];
                acc1 = fma2(h1p[2 * u], wq.x, acc1);
                acc1 = fma2(h1p[2 * u + 1], wq.y, acc1);
            }
            float a0, b0, a1, b1v;
            unpack2(acc0, a0, b0);
            unpack2(acc1, a1, b1v);
            float w3a = s_w3[jj], w3b = s_w3[jj + 1];
            oA = fmaf(fmaxf(a0, 0.0f), w3a, oA);
            oB = fmaf(fmaxf(b0, 0.0f), w3a, oB);
            oA = fmaf(fmaxf(a1, 0.0f), w3b, oA);
            oB = fmaf(fmaxf(b1v, 0.0f), w3b, oB);
        }
        out[ia] = 1.0f / (1.0f + expf(-oA));
        out[ib] = 1.0f / (1.0f + expf(-oB));
    }
}

// ---------------------------------------------------------------------------
// worklist apply: occ=tru at boundary; calc|=; conflict0 (buffers pre-zeroed)
// ---------------------------------------------------------------------------
__global__ void k_apply_wl(float* __restrict__ occ, const float* __restrict__ tru,
                           int R, int s) {
    const int total = g_count;
    const int stride = gridDim.x * blockDim.x;
    for (int t = blockIdx.x * blockDim.x + threadIdx.x; t < total; t += stride) {
        int p = g_wl[t];
        if (g_mB[p]) {
            float oi = occ[p];
            float ot = tru[p];
            occ[p] = ot;
            int k = p % R, j = (p / R) % R, i = p / (R * R);
            g_calc[(i * s) * RF * RF + (j * s) * RF + (k * s)] = 1;
            if ((oi - 0.5f) * (ot - 0.5f) < 0.0f) g_mA[p] = 1;
        }
    }
}

// ---------------------------------------------------------------------------
// worklist conflict-propagation iteration (cout may be null on last iter)
// ---------------------------------------------------------------------------
__global__ void k_conflict_wl(float* __restrict__ occ, const float* __restrict__ tru,
                              const unsigned char* __restrict__ cin,
                              unsigned char* __restrict__ cout, int R, int s) {
    const int total = g_count;
    const int stride = gridDim.x * blockDim.x;
    const int RR = R * R;
    for (int t = blockIdx.x * blockDim.x + threadIdx.x; t < total; t += stride) {
        int p = g_wl[t];
        int k = p % R, j = (p / R) % R, i = p / RR;
        int cidx = (i * s) * RF * RF + (j * s) * RF + (k * s);
        if (g_calc[cidx]) continue;
        int z0 = i > 0 ? i - 1 : 0, z1 = i < R - 1 ? i + 1 : R - 1;
        int y0 = j > 0 ? j - 1 : 0, y1 = j < R - 1 ? j + 1 : R - 1;
        int x0 = k > 0 ? k - 1 : 0, x1 = k < R - 1 ? k + 1 : R - 1;
        unsigned char nbr = 0;
        for (int z = z0; z <= z1 && !nbr; z++)
            for (int y = y0; y <= y1 && !nbr; y++)
                for (int x = x0; x <= x1; x++)
                    if (cin[z * RR + y * R + x]) { nbr = 1; break; }
        if (nbr) {
            float oi = occ[p];
            float ot = tru[p];
            occ[p] = ot;
            g_calc[cidx] = 1;
            if (cout != nullptr && (oi - 0.5f) * (ot - 0.5f) < 0.0f) cout[p] = 1;
        }
    }
}

// ---------------------------------------------------------------------------
// host driver
// ---------------------------------------------------------------------------
static inline int blocks_for(int n, int t) { return (n + t - 1) / t; }

extern "C" void kernel_launch(void* const* d_in, const int* in_sizes, int n_in,
                              void* d_out, int out_size) {
    const float* w1 = (const float*)d_in[0];
    const float* b1 = (const float*)d_in[1];
    const float* w2 = (const float*)d_in[2];
    const float* b2 = (const float*)d_in[3];
    const float* w3 = (const float*)d_in[4];
    const float* b3 = (const float*)d_in[5];
    float* out = (float*)d_out;

    float *bufA, *bufB, *tru;
    unsigned char *mA, *mC;
    cudaGetSymbolAddress((void**)&bufA, g_bufA);
    cudaGetSymbolAddress((void**)&bufB, g_bufB);
    cudaGetSymbolAddress((void**)&tru, g_true);
    cudaGetSymbolAddress((void**)&mA, g_mA);
    cudaGetSymbolAddress((void**)&mC, g_mC);

    // init calc lattice + seed dense 17^3 worklist
    k_init_calc<<<blocks_for(NF, 256), 256>>>();
    // level 0: dense 17^3 MLP
    k_mlp_list<<<64, 128>>>(w1, b1, w2, b2, w3, b3, bufA, 17, 8);

    struct Lv { int R, Rp, s; float* prev; float* occ; };
    Lv levels[3] = {
        {33, 17, 4, bufA, bufB},
        {65, 33, 2, bufB, bufA},
        {129, 65, 1, bufA, out},
    };

    for (int L = 0; L < 3; L++) {
        int R = levels[L].R, Rp = levels[L].Rp, s = levels[L].s;
        float* prev = levels[L].prev;
        float* occ = levels[L].occ;
        int tb = (R + 7) / 8;
        dim3 tgrid(tb, tb, tb), tblk(8, 8, 8);

        k_up_boundary<<<tgrid, tblk>>>(prev, occ, R, Rp, s);
        k_dilate2_scan<<<tgrid, tblk>>>(R);
        k_mlp_list<<<444, 128>>>(w1, b1, w2, b2, w3, b3, tru, R, s);
        k_apply_wl<<<232, 256>>>(occ, tru, R, s);
        k_conflict_wl<<<232, 256>>>(occ, tru, mA, mC, R, s);
        k_conflict_wl<<<232, 256>>>(occ, tru, mC, nullptr, R, s);
    }
}

// round 12
// speedup vs baseline: 1.0043x; 1.0043x over previous
#include <cuda_runtime.h>
#include <math.h>

#define RF 129
#define NF (RF*RF*RF)
#define H 64

// ---- scratch (device globals; no allocations allowed) ----
__device__ float g_bufA[NF];
__device__ float g_bufB[NF];
__device__ float g_true[NF];
__device__ unsigned char g_calc[NF];   // "calculated" at full 129^3 lattice
__device__ unsigned char g_mB[NF];     // boundary mask
__device__ unsigned char g_mA[NF];     // conflict buffer 0
__device__ unsigned char g_mC[NF];     // conflict buffer 1
__device__ int g_wl[NF];               // worklist of active voxel indices
__device__ int g_count;                // worklist length

// ---- packed fp32x2 helpers (Blackwell FFMA2 path) ----
__device__ __forceinline__ unsigned long long pack2(float a, float b) {
    unsigned long long r;
    asm("mov.b64 %0, {%1, %2};" : "=l"(r) : "f"(a), "f"(b));
    return r;
}
__device__ __forceinline__ unsigned long long fma2(unsigned long long a,
                                                   unsigned long long b,
                                                   unsigned long long c) {
    unsigned long long r;
    asm("fma.rn.f32x2 %0, %1, %2, %3;" : "=l"(r) : "l"(a), "l"(b), "l"(c));
    return r;
}
__device__ __forceinline__ void unpack2(unsigned long long v, float& a, float& b) {
    asm("mov.b64 {%0, %1}, %2;" : "=f"(a), "=f"(b) : "l"(v));
}

// ---------------------------------------------------------------------------
// init: calculated seed lattice (::8) + seed worklist with dense 17^3 indices
// ---------------------------------------------------------------------------
__global__ void k_init_calc() {
    int idx = blockIdx.x * blockDim.x + threadIdx.x;
    if (idx >= NF) return;
    int k = idx % RF;
    int j = (idx / RF) % RF;
    int i = idx / (RF * RF);
    g_calc[idx] = ((i & 7) == 0 && (j & 7) == 0 && (k & 7) == 0) ? 1 : 0;
    if (idx < 17 * 17 * 17) g_wl[idx] = idx;
    if (idx == 0) g_count = 17 * 17 * 17;
}

// ---------------------------------------------------------------------------
// FUSED: upsample (exact half-step trilinear) + fractional mask (shared tile,
// halo 1) + boundary = dilate(frac) & ~calc + zero conflict buffers.
// 8^3 interior tiles, 512 threads.
// ---------------------------------------------------------------------------
__global__ void k_up_boundary(const float* __restrict__ prev, float* __restrict__ occ,
                              int R, int Rp, int s) {
    __shared__ unsigned char s_frac[1000];   // 10^3
    const int bx = blockIdx.x * 8, by = blockIdx.y * 8, bz = blockIdx.z * 8;
    const int tid = threadIdx.x + threadIdx.y * 8 + threadIdx.z * 64;
    if (bx == 0 && by == 0 && bz == 0 && tid == 0) g_count = 0;  // reset worklist

    const int RpRp = Rp * Rp;
    for (int t = tid; t < 1000; t += 512) {
        int c = t % 10, b = (t / 10) % 10, a = t / 100;
        int qi = bz + a - 1, qj = by + b - 1, qk = bx + c - 1;
        unsigned char f = 0;
        if ((unsigned)qi < (unsigned)R && (unsigned)qj < (unsigned)R &&
            (unsigned)qk < (unsigned)R) {
            int i0 = qi >> 1, j0 = qj >> 1, k0 = qk >> 1;
            int di = qi & 1, dj = qj & 1, dk = qk & 1;
            int pos = 0, cnt = 0;
            for (int dz = 0; dz <= di; dz++)
                for (int dy = 0; dy <= dj; dy++)
                    for (int dx = 0; dx <= dk; dx++) {
                        float v = prev[(i0 + dz) * RpRp + (j0 + dy) * Rp + (k0 + dx)];
                        pos += (v > 0.5f) ? 1 : 0;
                        cnt++;
                    }
            f = (pos != 0 && pos != cnt) ? 1 : 0;
        }
        s_frac[t] = f;
    }
    __syncthreads();

    int i = bz + threadIdx.z, j = by + threadIdx.y, k = bx + threadIdx.x;
    if (i >= R || j >= R || k >= R) return;
    int idx = i * R * R + j * R + k;

    // exact interp (same summation order; validated rel_err 5e-8)
    {
        int i0 = i >> 1, j0 = j >> 1, k0 = k >> 1;
        int di = i & 1, dj = j & 1, dk = k & 1;
        float sum = 0.0f;
        int cnt = 0;
        for (int dz = 0; dz <= di; dz++)
            for (int dy = 0; dy <= dj; dy++)
                for (int dx = 0; dx <= dk; dx++) {
                    sum += prev[(i0 + dz) * RpRp + (j0 + dy) * Rp + (k0 + dx)];
                    cnt++;
                }
        occ[idx] = sum / (float)cnt;
    }
    g_mA[idx] = 0;
    g_mC[idx] = 0;

    // boundary = dilate27(frac) & ~calc[strided]
    unsigned char v = 0;
    int la = threadIdx.z, lb = threadIdx.y, lc = threadIdx.x;
    for (int a = 0; a < 3 && !v; a++)
        for (int b = 0; b < 3 && !v; b++)
            for (int c = 0; c < 3; c++)
                if (s_frac[(la + a) * 100 + (lb + b) * 10 + (lc + c)]) { v = 1; break; }
    if (v && g_calc[(i * s) * RF * RF + (j * s) * RF + (k * s)]) v = 0;
    g_mB[idx] = v;
}

// ---------------------------------------------------------------------------
// FUSED: dilate^2(boundary) + worklist append. Shared tile halo 2 (12^3),
// whole-block early exit when the window is empty.
// ---------------------------------------------------------------------------
__global__ void k_dilate2_scan(int R) {
    __shared__ unsigned char s_m[1728];   // 12^3
    __shared__ unsigned char s_d[1000];   // 10^3
    const int bx = blockIdx.x * 8, by = blockIdx.y * 8, bz = blockIdx.z * 8;
    const int tid = threadIdx.x + threadIdx.y * 8 + threadIdx.z * 64;
    const int RR = R * R;

    int any = 0;
    for (int t = tid; t < 1728; t += 512) {
        int c = t % 12, b = (t / 12) % 12, a = t / 144;
        int qi = bz + a - 2, qj = by + b - 2, qk = bx + c - 2;
        unsigned char val = 0;
        if ((unsigned)qi < (unsigned)R && (unsigned)qj < (unsigned)R &&
            (unsigned)qk < (unsigned)R)
            val = g_mB[qi * RR + qj * R + qk];
        s_m[t] = val;
        any |= val;
    }
    if (__syncthreads_or(any) == 0) return;   // empty window: no work

    for (int t = tid; t < 1000; t += 512) {
        int c = t % 10, b = (t / 10) % 10, a = t / 100;
        unsigned char v = 0;
        for (int da = 0; da < 3 && !v; da++)
            for (int db = 0; db < 3 && !v; db++)
                for (int dc = 0; dc < 3; dc++)
                    if (s_m[(a + da) * 144 + (b + db) * 12 + (c + dc)]) { v = 1; break; }
        s_d[t] = v;
    }
    __syncthreads();

    int i = bz + threadIdx.z, j = by + threadIdx.y, k = bx + threadIdx.x;
    unsigned char v = 0;
    int idx = 0;
    if (i < R && j < R && k < R) {
        idx = i * RR + j * R + k;
        int la = threadIdx.z, lb = threadIdx.y, lc = threadIdx.x;
        for (int a = 0; a < 3 && !v; a++)
            for (int b = 0; b < 3 && !v; b++)
                for (int c = 0; c < 3; c++)
                    if (s_d[(la + a) * 100 + (lb + b) * 10 + (lc + c)]) { v = 1; break; }
    }
    unsigned ballot = __ballot_sync(0xffffffffu, v != 0);
    if (v) {
        int lane = tid & 31;
        int leader = __ffs(ballot) - 1;
        int base = 0;
        if (lane == leader) base = atomicAdd(&g_count, __popc(ballot));
        base = __shfl_sync(0xffffffffu, base, leader);
        g_wl[base + __popc(ballot & ((1u << lane) - 1u))] = idx;
    }
}

// ---------------------------------------------------------------------------
// worklist MLP: 2 points/thread, packed fp32x2 FMA with pre-duplicated packed
// weights in shared (no pack2 in the hot loop), 2-accumulator ILP, grid-stride.
// s_w2d is 16B-aligned: the ulonglong2 (LDS.128) loads REQUIRE it.
// ---------------------------------------------------------------------------
__global__ void __launch_bounds__(128, 2)
k_mlp_list(const float* __restrict__ w1, const float* __restrict__ b1,
           const float* __restrict__ w2, const float* __restrict__ b2,
           const float* __restrict__ w3, const float* __restrict__ b3,
           float* __restrict__ out, int R, int s) {
    __shared__ float s_w1[3 * H];
    __shared__ float s_b1[H];
    __shared__ float s_b2[H];
    __shared__ float s_w3[H];
    __shared__ float s_b3f;
    __shared__ __align__(16) unsigned long long s_w2d[H * H];  // dup packed (w,w)

    const int count = g_count;
    const int npairs = (count + 1) >> 1;
    if ((int)(blockIdx.x * blockDim.x) >= npairs) return;  // tail blocks

    for (int t = threadIdx.x; t < 3 * H; t += blockDim.x) s_w1[t] = w1[t];
    for (int t = threadIdx.x; t < H; t += blockDim.x) {
        s_b1[t] = b1[t];
        s_b2[t] = b2[t];
        s_w3[t] = w3[t];
    }
    for (int t = threadIdx.x; t < H * H; t += blockDim.x) {
        int jj = t >> 6, u = t & 63;             // s_w2d[jj*H+u] = dup(w2[u][jj])
        float w = w2[u * H + jj];
        s_w2d[t] = pack2(w, w);
    }
    if (threadIdx.x == 0) s_b3f = b3[0];
    __syncthreads();

    const int stride = gridDim.x * blockDim.x;
    for (int pair = blockIdx.x * blockDim.x + threadIdx.x; pair < npairs;
         pair += stride) {
        int ia = g_wl[2 * pair];
        int ib = (2 * pair + 1 < count) ? g_wl[2 * pair + 1] : ia;

        const float sc = 2.0f / 129.0f;
        int ka = ia % R, ja = (ia / R) % R, iia = ia / (R * R);
        int kb = ib % R, jb = (ib / R) % R, iib = ib / (R * R);
        float pxa = ((float)(ka * s) + 0.5f) * sc - 1.0f;
        float pya = ((float)(ja * s) + 0.5f) * sc - 1.0f;
        float pza = ((float)(iia * s) + 0.5f) * sc - 1.0f;
        float pxb = ((float)(kb * s) + 0.5f) * sc - 1.0f;
        float pyb = ((float)(jb * s) + 0.5f) * sc - 1.0f;
        float pzb = ((float)(iib * s) + 0.5f) * sc - 1.0f;

        // layer 1: scalar, packed into f32x2
        unsigned long long h1p[H];
#pragma unroll
        for (int u = 0; u < H; u++) {
            float wx = s_w1[u], wy = s_w1[H + u], wz = s_w1[2 * H + u], bb = s_b1[u];
            float va = fmaf(pza, wz, fmaf(pya, wy, fmaf(pxa, wx, bb)));
            float vb = fmaf(pzb, wz, fmaf(pyb, wy, fmaf(pxb, wx, bb)));
            h1p[u] = pack2(fmaxf(va, 0.0f), fmaxf(vb, 0.0f));
        }

        // layer 2 + output accumulate: pure LDS.128 + fma2, 2 chains
        float oA = s_b3f, oB = s_b3f;
#pragma unroll 1
        for (int jj = 0; jj < H; jj += 2) {
            unsigned long long acc0 = pack2(s_b2[jj], s_b2[jj]);
            unsigned long long acc1 = pack2(s_b2[jj + 1], s_b2[jj + 1]);
            const ulonglong2* r0 = (const ulonglong2*)&s_w2d[jj * H];
            const ulonglong2* r1 = (const ulonglong2*)&s_w2d[jj * H + H];
#pragma unroll
            for (int u = 0; u < H / 2; u++) {
                ulonglong2 w0 = r0[u];
                acc0 = fma2(h1p[2 * u], w0.x, acc0);
                acc0 = fma2(h1p[2 * u + 1], w0.y, acc0);
                ulonglong2 wq = r1[u];
                acc1 = fma2(h1p[2 * u], wq.x, acc1);
                acc1 = fma2(h1p[2 * u + 1], wq.y, acc1);
            }
            float a0, b0, a1, b1v;
            unpack2(acc0, a0, b0);
            unpack2(acc1, a1, b1v);
            float w3a = s_w3[jj], w3b = s_w3[jj + 1];
            oA = fmaf(fmaxf(a0, 0.0f), w3a, oA);
            oB = fmaf(fmaxf(b0, 0.0f), w3a, oB);
            oA = fmaf(fmaxf(a1, 0.0f), w3b, oA);
            oB = fmaf(fmaxf(b1v, 0.0f), w3b, oB);
        }
        out[ia] = 1.0f / (1.0f + expf(-oA));
        out[ib] = 1.0f / (1.0f + expf(-oB));
    }
}

// ---------------------------------------------------------------------------
// worklist apply: occ=tru at boundary; calc|=; conflict0 (buffers pre-zeroed)
// ---------------------------------------------------------------------------
__global__ void k_apply_wl(float* __restrict__ occ, const float* __restrict__ tru,
                           int R, int s) {
    const int total = g_count;
    const int stride = gridDim.x * blockDim.x;
    for (int t = blockIdx.x * blockDim.x + threadIdx.x; t < total; t += stride) {
        int p = g_wl[t];
        if (g_mB[p]) {
            float oi = occ[p];
            float ot = tru[p];
            occ[p] = ot;
            int k = p % R, j = (p / R) % R, i = p / (R * R);
            g_calc[(i * s) * RF * RF + (j * s) * RF + (k * s)] = 1;
            if ((oi - 0.5f) * (ot - 0.5f) < 0.0f) g_mA[p] = 1;
        }
    }
}

// ---------------------------------------------------------------------------
// worklist conflict-propagation iteration (cout may be null on last iter)
// ---------------------------------------------------------------------------
__global__ void k_conflict_wl(float* __restrict__ occ, const float* __restrict__ tru,
                              const unsigned char* __restrict__ cin,
                              unsigned char* __restrict__ cout, int R, int s) {
    const int total = g_count;
    const int stride = gridDim.x * blockDim.x;
    const int RR = R * R;
    for (int t = blockIdx.x * blockDim.x + threadIdx.x; t < total; t += stride) {
        int p = g_wl[t];
        int k = p % R, j = (p / R) % R, i = p / RR;
        int cidx = (i * s) * RF * RF + (j * s) * RF + (k * s);
        if (g_calc[cidx]) continue;
        int z0 = i > 0 ? i - 1 : 0, z1 = i < R - 1 ? i + 1 : R - 1;
        int y0 = j > 0 ? j - 1 : 0, y1 = j < R - 1 ? j + 1 : R - 1;
        int x0 = k > 0 ? k - 1 : 0, x1 = k < R - 1 ? k + 1 : R - 1;
        unsigned char nbr = 0;
        for (int z = z0; z <= z1 && !nbr; z++)
            for (int y = y0; y <= y1 && !nbr; y++)
                for (int x = x0; x <= x1; x++)
                    if (cin[z * RR + y * R + x]) { nbr = 1; break; }
        if (nbr) {
            float oi = occ[p];
            float ot = tru[p];
            occ[p] = ot;
            g_calc[cidx] = 1;
            if (cout != nullptr && (oi - 0.5f) * (ot - 0.5f) < 0.0f) cout[p] = 1;
        }
    }
}

// ---------------------------------------------------------------------------
// host driver
// ---------------------------------------------------------------------------
static inline int blocks_for(int n, int t) { return (n + t - 1) / t; }

extern "C" void kernel_launch(void* const* d_in, const int* in_sizes, int n_in,
                              void* d_out, int out_size) {
    const float* w1 = (const float*)d_in[0];
    const float* b1 = (const float*)d_in[1];
    const float* w2 = (const float*)d_in[2];
    const float* b2 = (const float*)d_in[3];
    const float* w3 = (const float*)d_in[4];
    const float* b3 = (const float*)d_in[5];
    float* out = (float*)d_out;

    float *bufA, *bufB, *tru;
    unsigned char *mA, *mC;
    cudaGetSymbolAddress((void**)&bufA, g_bufA);
    cudaGetSymbolAddress((void**)&bufB, g_bufB);
    cudaGetSymbolAddress((void**)&tru, g_true);
    cudaGetSymbolAddress((void**)&mA, g_mA);
    cudaGetSymbolAddress((void**)&mC, g_mC);

    // init calc lattice + seed dense 17^3 worklist
    k_init_calc<<<blocks_for(NF, 256), 256>>>();
    // level 0: dense 17^3 MLP
    k_mlp_list<<<64, 128>>>(w1, b1, w2, b2, w3, b3, bufA, 17, 8);

    struct Lv { int R, Rp, s; float* prev; float* occ; };
    Lv levels[3] = {
        {33, 17, 4, bufA, bufB},
        {65, 33, 2, bufB, bufA},
        {129, 65, 1, bufA, out},
    };

    for (int L = 0; L < 3; L++) {
        int R = levels[L].R, Rp = levels[L].Rp, s = levels[L].s;
        float* prev = levels[L].prev;
        float* occ = levels[L].occ;
        int tb = (R + 7) / 8;
        dim3 tgrid(tb, tb, tb), tblk(8, 8, 8);

        k_up_boundary<<<tgrid, tblk>>>(prev, occ, R, Rp, s);
        k_dilate2_scan<<<tgrid, tblk>>>(R);
        k_mlp_list<<<444, 128>>>(w1, b1, w2, b2, w3, b3, tru, R, s);
        k_apply_wl<<<232, 256>>>(occ, tru, R, s);
        k_conflict_wl<<<232, 256>>>(occ, tru, mA, mC, R, s);
        k_conflict_wl<<<232, 256>>>(occ, tru, mC, nullptr, R, s);
    }
}